// round 1
// baseline (speedup 1.0000x reference)
#include <cuda_runtime.h>

// LSTM: B=4096, T=512, IN=64, H=10 (4H=40 gates, PyTorch order i,f,g,o)
// out = concat( output[B][T][H], h_last[B][H] ) as float32.

#define BB   4096
#define TT   512
#define IND  64
#define HH   10
#define NB   32          // batch elements per block
#define NTH  320         // 10 warps: warp j (hidden unit), lane b (local batch)

__device__ __forceinline__ float sigm_fast(float x) {
    // 1 / (1 + e^-x), fast approx exp + fast div (~1e-6 rel err)
    return __fdividef(1.0f, 1.0f + __expf(-x));
}
__device__ __forceinline__ float tanh_fast(float x) {
    // 1 - 2/(e^{2x}+1); saturates correctly at +/-inf
    return 1.0f - 2.0f * __fdividef(1.0f, 1.0f + __expf(2.0f * x));
}

__global__ __launch_bounds__(NTH, 1)
void lstm_fused_kernel(const float* __restrict__ x,
                       const float* __restrict__ W_ih,
                       const float* __restrict__ W_hh,
                       const float* __restrict__ b_ih,
                       const float* __restrict__ b_hh,
                       float* __restrict__ out,
                       long long out_size)
{
    // Shared memory (≈41.5 KB total)
    __shared__ float4 xs[2][NB][17];            // x tile, double-buffered, pad 16->17
    __shared__ float4 wih4[40][16];             // W_ih rows as float4 (broadcast reads)
    __shared__ __align__(16) float whh[40][12]; // W_hh rows padded 10->12 (zeros)
    __shared__ __align__(16) float hs[NB][12];  // h state, padded 10->12 (zeros)
    __shared__ float outs[NB][81];              // 8-step output staging, pad 80->81

    const int tid = threadIdx.x;
    const int j   = tid >> 5;        // hidden unit 0..9  (== warp id)
    const int b   = tid & 31;        // local batch 0..31 (== lane)
    const int b0  = blockIdx.x * NB;

    // ---- load weights into shared ----
    const float4* wg = (const float4*)W_ih;     // 40*64 floats = 640 float4
    for (int idx = tid; idx < 640; idx += NTH)
        ((float4*)wih4)[idx] = wg[idx];

    for (int idx = tid; idx < 40 * 12; idx += NTH) {
        int g = idx / 12, c = idx - g * 12;
        whh[g][c] = (c < HH) ? W_hh[g * HH + c] : 0.0f;
    }
    for (int idx = tid; idx < NB * 12; idx += NTH)
        ((float*)hs)[idx] = 0.0f;

    // per-thread gate biases (b_ih + b_hh pre-summed)
    const float bI = b_ih[j]      + b_hh[j];
    const float bF = b_ih[j + 10] + b_hh[j + 10];
    const float bG = b_ih[j + 20] + b_hh[j + 20];
    const float bO = b_ih[j + 30] + b_hh[j + 30];

    // stage x tile for t=0
    const float4* x4 = (const float4*)x;        // row = 16 float4 per (b,t)
    for (int idx = tid; idx < NB * 16; idx += NTH) {
        int r = idx >> 4, c = idx & 15;
        xs[0][r][c] = x4[(size_t)(b0 + r) * (TT * 16) + c];
    }
    __syncthreads();

    float c_st = 0.0f;
    float h    = 0.0f;

    for (int t = 0; t < TT; ++t) {
        const int cur = t & 1;

        float a0 = bI, a1 = bF, a2 = bG, a3 = bO;

        // ---- input projection: 4 gates x 64 ----
        #pragma unroll
        for (int i4 = 0; i4 < 16; ++i4) {
            float4 xv = xs[cur][b][i4];
            float4 w0 = wih4[j     ][i4];
            float4 w1 = wih4[j + 10][i4];
            float4 w2 = wih4[j + 20][i4];
            float4 w3 = wih4[j + 30][i4];
            a0 = fmaf(xv.x, w0.x, fmaf(xv.y, w0.y, fmaf(xv.z, w0.z, fmaf(xv.w, w0.w, a0))));
            a1 = fmaf(xv.x, w1.x, fmaf(xv.y, w1.y, fmaf(xv.z, w1.z, fmaf(xv.w, w1.w, a1))));
            a2 = fmaf(xv.x, w2.x, fmaf(xv.y, w2.y, fmaf(xv.z, w2.z, fmaf(xv.w, w2.w, a2))));
            a3 = fmaf(xv.x, w3.x, fmaf(xv.y, w3.y, fmaf(xv.z, w3.z, fmaf(xv.w, w3.w, a3))));
        }

        // ---- recurrent projection: 4 gates x 10 (padded to 12) ----
        #pragma unroll
        for (int k4 = 0; k4 < 3; ++k4) {
            float4 hv = *(const float4*)&hs[b][k4 * 4];
            float4 w0 = *(const float4*)&whh[j     ][k4 * 4];
            float4 w1 = *(const float4*)&whh[j + 10][k4 * 4];
            float4 w2 = *(const float4*)&whh[j + 20][k4 * 4];
            float4 w3 = *(const float4*)&whh[j + 30][k4 * 4];
            a0 = fmaf(hv.x, w0.x, fmaf(hv.y, w0.y, fmaf(hv.z, w0.z, fmaf(hv.w, w0.w, a0))));
            a1 = fmaf(hv.x, w1.x, fmaf(hv.y, w1.y, fmaf(hv.z, w1.z, fmaf(hv.w, w1.w, a1))));
            a2 = fmaf(hv.x, w2.x, fmaf(hv.y, w2.y, fmaf(hv.z, w2.z, fmaf(hv.w, w2.w, a2))));
            a3 = fmaf(hv.x, w3.x, fmaf(hv.y, w3.y, fmaf(hv.z, w3.z, fmaf(hv.w, w3.w, a3))));
        }

        // ---- stage x for t+1 into the other buffer (overlaps with compute) ----
        if (t + 1 < TT) {
            for (int idx = tid; idx < NB * 16; idx += NTH) {
                int r = idx >> 4, c = idx & 15;
                xs[cur ^ 1][r][c] =
                    x4[(size_t)(b0 + r) * (TT * 16) + (size_t)(t + 1) * 16 + c];
            }
        }

        // ---- activations + state update ----
        float ig = sigm_fast(a0);
        float fg = sigm_fast(a1);
        float gg = tanh_fast(a2);
        float og = sigm_fast(a3);
        c_st = fmaf(fg, c_st, ig * gg);
        h    = og * tanh_fast(c_st);

        __syncthreads();                 // all hs reads (above) before hs writes
        hs[b][j] = h;
        outs[b][(t & 7) * HH + j] = h;
        __syncthreads();                 // hs/outs/xs[next] visible to everyone

        // ---- coalesced flush of 8 timesteps ----
        if ((t & 7) == 7) {
            const int tbase = t - 7;
            for (int idx = tid; idx < NB * 80; idx += NTH) {
                int r = idx / 80, c = idx - r * 80;
                out[(size_t)(b0 + r) * (TT * HH) + (size_t)tbase * HH + c] = outs[r][c];
            }
            // next write into outs happens only after the next step's first
            // __syncthreads(), so no extra barrier needed here.
        }
    }

    // ---- h_last ----
    const long long base = (long long)BB * TT * HH;
    const long long idx  = base + (long long)(b0 + b) * HH + j;
    if (idx < out_size)
        out[idx] = h;
}

extern "C" void kernel_launch(void* const* d_in, const int* in_sizes, int n_in,
                              void* d_out, int out_size)
{
    const float* x    = (const float*)d_in[0];
    const float* W_ih = (const float*)d_in[1];
    const float* W_hh = (const float*)d_in[2];
    const float* b_ih = (const float*)d_in[3];
    const float* b_hh = (const float*)d_in[4];
    float* out = (float*)d_out;

    dim3 grid(BB / NB);   // 128 blocks
    dim3 block(NTH);      // 320 threads
    lstm_fused_kernel<<<grid, block>>>(x, W_ih, W_hh, b_ih, b_hh, out,
                                       (long long)out_size);
}

// round 2
// speedup vs baseline: 2.4717x; 2.4717x over previous
#include <cuda_runtime.h>

// LSTM B=4096, T=512, IN=64, H=10. Split design:
//  K1: xg[b][t][j][gate] = x[b][t][:]·W_ih[g][:] + b_ih[g] + b_hh[g]   (big GEMM, f32x2 FMA)
//  K2: sequential scan, 3 batches per warp, h broadcast via shfl.

#define BB   4096
#define TT   512
#define IND  64
#define HH   10

// 335.5 MB scratch for the precomputed input projection (permuted layout:
// index = bt*40 + j*4 + gate_idx, gate_idx: 0=i 1=f 2=g 3=o)
__device__ float xg_buf[(size_t)BB * TT * 40];

// ---------------------------------------------------------------------------
// Kernel 1: input projection GEMM.  [2M rows x 64] * [64 x 40] + bias.
// Block: 128 threads, tile 64 rows x 40 gates, thread tile 4 rows x 5 gates.
// K accumulated pairwise with fma.rn.f32x2 (packed 2xfp32 per instruction).
// ---------------------------------------------------------------------------
__device__ __forceinline__ void fma2(unsigned long long& d,
                                     unsigned long long a,
                                     unsigned long long b) {
    asm("fma.rn.f32x2 %0, %1, %2, %0;" : "+l"(d) : "l"(a), "l"(b));
}

__global__ __launch_bounds__(128, 1)
void input_proj_kernel(const float* __restrict__ x,
                       const float* __restrict__ W_ih,
                       const float* __restrict__ b_ih,
                       const float* __restrict__ b_hh)
{
    __shared__ __align__(16) float2 xs[64][33];   // 64 rows x 32 k-pairs (+pad)
    __shared__ __align__(16) float2 ws[40][33];   // 40 gates x 32 k-pairs (+pad)

    const int tid  = threadIdx.x;
    const size_t row0 = (size_t)blockIdx.x * 64;

    // stage x tile (64 rows x 64 floats) as k-pairs
    const float4* x4 = (const float4*)(x + row0 * IND);
    for (int i = tid; i < 1024; i += 128) {
        int r = i >> 4, c = i & 15;
        float4 v = x4[r * 16 + c];
        xs[r][2 * c]     = make_float2(v.x, v.y);
        xs[r][2 * c + 1] = make_float2(v.z, v.w);
    }
    // stage W_ih (40 x 64) as k-pairs
    const float4* w4 = (const float4*)W_ih;
    for (int i = tid; i < 640; i += 128) {
        int r = i >> 4, c = i & 15;
        float4 v = w4[i];
        ws[r][2 * c]     = make_float2(v.x, v.y);
        ws[r][2 * c + 1] = make_float2(v.z, v.w);
    }
    __syncthreads();

    const int tx = tid & 7;      // gate group: gates g0..g0+4
    const int ty = tid >> 3;     // row group:  rows r0..r0+3
    const int g0 = tx * 5;
    const int r0 = ty * 4;

    // biases for my 5 gates
    float bsum[5];
    #pragma unroll
    for (int g = 0; g < 5; ++g)
        bsum[g] = b_ih[g0 + g] + b_hh[g0 + g];

    unsigned long long acc[4][5];
    #pragma unroll
    for (int r = 0; r < 4; ++r)
        #pragma unroll
        for (int g = 0; g < 5; ++g)
            acc[r][g] = 0ull;   // two packed +0.0f

    #pragma unroll 8
    for (int kp = 0; kp < 32; ++kp) {
        unsigned long long xa[4], wb[5];
        #pragma unroll
        for (int r = 0; r < 4; ++r)
            xa[r] = *(const unsigned long long*)&xs[r0 + r][kp];
        #pragma unroll
        for (int g = 0; g < 5; ++g)
            wb[g] = *(const unsigned long long*)&ws[g0 + g][kp];
        #pragma unroll
        for (int r = 0; r < 4; ++r)
            #pragma unroll
            for (int g = 0; g < 5; ++g)
                fma2(acc[r][g], xa[r], wb[g]);
    }

    // epilogue: reduce pairs, add bias, stage permuted into smem, flush coalesced
    __syncthreads();
    float* outsm = (float*)xs;   // reuse: 64*40 floats = 10.2 KB (xs is 16.9 KB)
    #pragma unroll
    for (int r = 0; r < 4; ++r) {
        #pragma unroll
        for (int g = 0; g < 5; ++g) {
            float lo, hi;
            asm("mov.b64 {%0, %1}, %2;" : "=f"(lo), "=f"(hi) : "l"(acc[r][g]));
            float v = lo + hi + bsum[g];
            int gg = g0 + g;
            int j  = gg % 10;
            int gi = gg / 10;
            outsm[(r0 + r) * 40 + j * 4 + gi] = v;
        }
    }
    __syncthreads();

    float4* dst = (float4*)(xg_buf + row0 * 40);
    const float4* src = (const float4*)outsm;
    for (int i = tid; i < 640; i += 128)
        dst[i] = src[i];
}

// ---------------------------------------------------------------------------
// Kernel 2: recurrent scan. 3 batches per warp (lanes 0..29 active).
// Lane (group,j): group = lane/10 -> batch, j = lane%10 -> hidden unit,
// computing all 4 gates of unit j. h broadcast per step via shfl.
// ---------------------------------------------------------------------------
__device__ __forceinline__ float sigm_fast(float x) {
    return __fdividef(1.0f, 1.0f + __expf(-x));
}
__device__ __forceinline__ float tanh_fast(float x) {
    return 1.0f - 2.0f * __fdividef(1.0f, 1.0f + __expf(2.0f * x));
}

#define K2_THREADS 64          // 2 warps -> 6 batches per block
#define K2_BATCH_PER_BLOCK 6

__global__ __launch_bounds__(K2_THREADS, 1)
void lstm_scan_kernel(const float* __restrict__ W_hh,
                      float* __restrict__ out)
{
    const int lane  = threadIdx.x & 31;
    const int warp  = threadIdx.x >> 5;
    int group = lane / 10;                 // 0,1,2 (lanes 30,31 -> 3)
    const bool active = (lane < 30);
    if (!active) group = 2;
    const int j = active ? (lane - group * 10) : 0;

    const int b = blockIdx.x * K2_BATCH_PER_BLOCK + warp * 3 + group;
    const bool valid = active && (b < BB);
    const int b_eff = valid ? b : 0;

    // recurrent weights for my unit's 4 gates (rows j, j+10, j+20, j+30)
    float wI[10], wF[10], wG[10], wO[10];
    #pragma unroll
    for (int k = 0; k < 10; ++k) {
        wI[k] = W_hh[(j)      * HH + k];
        wF[k] = W_hh[(j + 10) * HH + k];
        wG[k] = W_hh[(j + 20) * HH + k];
        wO[k] = W_hh[(j + 30) * HH + k];
    }

    // xg stream: one float4 (i,f,g,o pre-biased) per step
    const float4* xgp = (const float4*)(xg_buf + (size_t)b_eff * TT * 40) + j;

    // prefetch 8 steps deep
    float4 pf[8];
    #pragma unroll
    for (int d = 0; d < 8; ++d)
        pf[d] = xgp[(size_t)d * 10];

    float h = 0.0f, c = 0.0f;
    float* outp = out + (size_t)b_eff * TT * HH + j;
    const int srcbase = group * 10;

    for (int t = 0; t < TT; t += 8) {
        #pragma unroll
        for (int u = 0; u < 8; ++u) {
            float4 xv = pf[u];
            int tn = t + u + 8;
            if (tn < TT)                       // uniform branch
                pf[u] = xgp[(size_t)tn * 10];

            float aI = xv.x, aF = xv.y, aG = xv.z, aO = xv.w;
            #pragma unroll
            for (int k = 0; k < 10; ++k) {
                float hk = __shfl_sync(0xffffffffu, h, srcbase + k);
                aI = fmaf(hk, wI[k], aI);
                aF = fmaf(hk, wF[k], aF);
                aG = fmaf(hk, wG[k], aG);
                aO = fmaf(hk, wO[k], aO);
            }
            float ig = sigm_fast(aI);
            float fg = sigm_fast(aF);
            float gg = tanh_fast(aG);
            float og = sigm_fast(aO);
            c = fmaf(fg, c, ig * gg);
            h = og * tanh_fast(c);

            if (valid)
                outp[(size_t)(t + u) * HH] = h;
        }
    }

    if (valid)
        out[(size_t)BB * TT * HH + (size_t)b * HH + j] = h;
}

// ---------------------------------------------------------------------------
extern "C" void kernel_launch(void* const* d_in, const int* in_sizes, int n_in,
                              void* d_out, int out_size)
{
    const float* x    = (const float*)d_in[0];
    const float* W_ih = (const float*)d_in[1];
    const float* W_hh = (const float*)d_in[2];
    const float* b_ih = (const float*)d_in[3];
    const float* b_hh = (const float*)d_in[4];
    float* out = (float*)d_out;

    // K1: 2,097,152 rows / 64 per block
    input_proj_kernel<<<(BB * TT) / 64, 128>>>(x, W_ih, b_ih, b_hh);

    // K2: 4096 batches / 6 per block
    int grid2 = (BB + K2_BATCH_PER_BLOCK - 1) / K2_BATCH_PER_BLOCK;  // 683
    lstm_scan_kernel<<<grid2, K2_THREADS>>>(W_hh, out);
}

// round 3
// speedup vs baseline: 3.0088x; 1.2173x over previous
#include <cuda_runtime.h>

// LSTM B=4096, T=512, IN=64, H=10.
//  K1 (x4 grid quarters): xg[bt][j*4+gate] = x[bt][:]·W_ih + b_ih + b_hh
//  K2: sequential scan, 3 batches/warp, h broadcast via shfl.

#define BB   4096
#define TT   512
#define IND  64
#define HH   10

// 335.5 MB scratch: permuted layout idx = bt*40 + j*4 + gate (0=i 1=f 2=g 3=o)
__device__ float xg_buf[(size_t)BB * TT * 40];

__device__ __forceinline__ void fma2(unsigned long long& d,
                                     unsigned long long a,
                                     unsigned long long b) {
    asm("fma.rn.f32x2 %0, %1, %2, %0;" : "+l"(d) : "l"(a), "l"(b));
}

// ---------------------------------------------------------------------------
// K1: [2M x 64] * [64 x 40] + bias.  128 threads, 128 rows/block.
// Thread tile: 8 rows x 5 gates. k consumed as float4 chunks (2 f32x2/load).
// x tile XOR-swizzled so the 4 ty-groups in a warp hit distinct banks.
// ---------------------------------------------------------------------------
__global__ __launch_bounds__(128, 3)
void input_proj_kernel(const float* __restrict__ x,
                       const float* __restrict__ W_ih,
                       const float* __restrict__ b_ih,
                       const float* __restrict__ b_hh,
                       int block0)
{
    __shared__ __align__(16) float4 xs[128][17];   // 128 rows x 16 chunks (+pad)
    __shared__ __align__(16) float4 ws[40][17];    // 40 gates x 16 chunks (+pad)

    const int tid = threadIdx.x;
    const size_t row0 = (size_t)(blockIdx.x + block0) * 128;

    // stage x tile (swizzle column by (row>>3)&3)
    const float4* x4 = (const float4*)(x + row0 * IND);
    #pragma unroll
    for (int i = tid; i < 2048; i += 128) {
        int r = i >> 4, c = i & 15;
        xs[r][c ^ ((r >> 3) & 3)] = __ldcs(&x4[i]);
    }
    // stage W_ih (40 x 64)
    const float4* w4 = (const float4*)W_ih;
    for (int i = tid; i < 640; i += 128)
        ws[i >> 4][i & 15] = w4[i];
    __syncthreads();

    const int tx = tid & 7;          // gate group (5 gates)
    const int ty = tid >> 3;         // row group  (8 rows)
    const int g0 = tx * 5;
    const int r0 = ty * 8;
    const int swz = ty & 3;

    float bsum[5];
    #pragma unroll
    for (int g = 0; g < 5; ++g)
        bsum[g] = b_ih[g0 + g] + b_hh[g0 + g];

    unsigned long long acc[8][5];
    #pragma unroll
    for (int r = 0; r < 8; ++r)
        #pragma unroll
        for (int g = 0; g < 5; ++g)
            acc[r][g] = 0ull;

    #pragma unroll 2
    for (int kc = 0; kc < 16; ++kc) {
        float4 xa[8], wb[5];
        const int xcol = kc ^ swz;
        #pragma unroll
        for (int r = 0; r < 8; ++r) xa[r] = xs[r0 + r][xcol];
        #pragma unroll
        for (int g = 0; g < 5; ++g) wb[g] = ws[g0 + g][kc];

        #pragma unroll
        for (int r = 0; r < 8; ++r) {
            const unsigned long long* xp = (const unsigned long long*)&xa[r];
            #pragma unroll
            for (int g = 0; g < 5; ++g) {
                const unsigned long long* wp = (const unsigned long long*)&wb[g];
                fma2(acc[r][g], xp[0], wp[0]);
                fma2(acc[r][g], xp[1], wp[1]);
            }
        }
    }

    // epilogue: reduce pairs, bias, permute to [j*4+gate], coalesced flush
    __syncthreads();
    float* osm = (float*)xs;    // 128*40 floats = 20.5 KB, fits in xs
    #pragma unroll
    for (int r = 0; r < 8; ++r) {
        #pragma unroll
        for (int g = 0; g < 5; ++g) {
            float lo, hi;
            asm("mov.b64 {%0, %1}, %2;" : "=f"(lo), "=f"(hi) : "l"(acc[r][g]));
            float v = lo + hi + bsum[g];
            int gg = g0 + g;
            int j  = gg % 10;
            int gi = gg / 10;
            osm[(r0 + r) * 40 + j * 4 + gi] = v;
        }
    }
    __syncthreads();

    float4* dst = (float4*)(xg_buf + row0 * 40);
    const float4* src = (const float4*)osm;
    #pragma unroll
    for (int i = tid; i < 1280; i += 128)
        __stcs(&dst[i], src[i]);
}

// ---------------------------------------------------------------------------
// K2: recurrent scan. Lanes 0..29: group=lane/10 (batch), j=lane%10 (unit).
// ---------------------------------------------------------------------------
__device__ __forceinline__ float sigm_fast(float x) {
    return __fdividef(1.0f, 1.0f + __expf(-x));
}
__device__ __forceinline__ float tanh_fast(float x) {
    return 1.0f - 2.0f * __fdividef(1.0f, 1.0f + __expf(2.0f * x));
}

#define K2_THREADS 64
#define K2_BATCH_PER_BLOCK 6

__global__ __launch_bounds__(K2_THREADS, 1)
void lstm_scan_kernel(const float* __restrict__ W_hh,
                      float* __restrict__ out)
{
    const int lane = threadIdx.x & 31;
    const int warp = threadIdx.x >> 5;
    int group = lane / 10;
    const bool active = (lane < 30);
    if (!active) group = 2;
    const int j = active ? (lane - group * 10) : 0;

    const int b = blockIdx.x * K2_BATCH_PER_BLOCK + warp * 3 + group;
    const bool valid = active && (b < BB);
    const int b_eff = valid ? b : 0;

    float wI[10], wF[10], wG[10], wO[10];
    #pragma unroll
    for (int k = 0; k < 10; ++k) {
        wI[k] = W_hh[(j)      * HH + k];
        wF[k] = W_hh[(j + 10) * HH + k];
        wG[k] = W_hh[(j + 20) * HH + k];
        wO[k] = W_hh[(j + 30) * HH + k];
    }

    const float4* xgp = (const float4*)(xg_buf + (size_t)b_eff * TT * 40) + j;

    float4 pf[8];
    #pragma unroll
    for (int d = 0; d < 8; ++d)
        pf[d] = __ldcs(&xgp[(size_t)d * 10]);

    float h = 0.0f, c = 0.0f;
    float* outp = out + (size_t)b_eff * TT * HH + j;
    const int srcbase = group * 10;

    for (int t = 0; t < TT; t += 8) {
        #pragma unroll
        for (int u = 0; u < 8; ++u) {
            float4 xv = pf[u];
            int tn = t + u + 8;
            if (tn < TT)
                pf[u] = __ldcs(&xgp[(size_t)tn * 10]);

            float aI = xv.x, aF = xv.y, aG = xv.z, aO = xv.w;
            #pragma unroll
            for (int k = 0; k < 10; ++k) {
                float hk = __shfl_sync(0xffffffffu, h, srcbase + k);
                aI = fmaf(hk, wI[k], aI);
                aF = fmaf(hk, wF[k], aF);
                aG = fmaf(hk, wG[k], aG);
                aO = fmaf(hk, wO[k], aO);
            }
            float ig = sigm_fast(aI);
            float fg = sigm_fast(aF);
            float gg = tanh_fast(aG);
            float og = sigm_fast(aO);
            c = fmaf(fg, c, ig * gg);
            h = og * tanh_fast(c);

            if (valid)
                __stcs(&outp[(size_t)(t + u) * HH], h);
        }
    }

    if (valid)
        out[(size_t)BB * TT * HH + (size_t)b * HH + j] = h;
}

// ---------------------------------------------------------------------------
extern "C" void kernel_launch(void* const* d_in, const int* in_sizes, int n_in,
                              void* d_out, int out_size)
{
    const float* x    = (const float*)d_in[0];
    const float* W_ih = (const float*)d_in[1];
    const float* W_hh = (const float*)d_in[2];
    const float* b_ih = (const float*)d_in[3];
    const float* b_hh = (const float*)d_in[4];
    float* out = (float*)d_out;

    // K1: 16384 blocks total, split into 4 launches so ncu's 6th-launch
    // capture window lands on a K1 quarter instead of always K2.
    const int total_blocks = (BB * TT) / 128;       // 16384
    const int q = total_blocks / 4;                 // 4096
    for (int i = 0; i < 4; ++i)
        input_proj_kernel<<<q, 128>>>(x, W_ih, b_ih, b_hh, i * q);

    int grid2 = (BB + K2_BATCH_PER_BLOCK - 1) / K2_BATCH_PER_BLOCK;  // 683
    lstm_scan_kernel<<<grid2, K2_THREADS>>>(W_hh, out);
}